// round 4
// baseline (speedup 1.0000x reference)
#include <cuda_runtime.h>
#include <math.h>

// ---------------------------------------------------------------------------
// NUFFT adjoint (Kaiser-Bessel gridding) for GB300 — round 4 (R3 + build fix)
//   zero grid -> scatter (red.global.add.v4.f32) ->
//   four-step (32x32) register IFFT over kx (pruned output rows) ->
//   four-step register IFFT over ky + fused fftshift/crop/deapod epilogue.
// FFT: each 1024-pt IFFT = FFT32(regs) -> twiddle -> FFT32(regs), with
// XOR-swizzled smem (conflict-free column & row passes). 8 FFTs/block,
// 256 threads, 65.6 KB smem -> multiple blocks/SM.
// ---------------------------------------------------------------------------

#define KGRID   1024
#define NIMG    512
#define MPTS    200000
#define BATCH   8
#define JW      6
#define BETA_F  14.04f
#define PI_F    3.14159265358979f

#define GRID_F2 (KGRID * KGRID * BATCH)   // 64 MB
#define PITCH   1025                      // smem row pitch (float2)

__device__ float2 g_grid[GRID_F2];

// ---------------------------------------------------------------------------
__device__ __forceinline__ float bessel_i0(float x)
{
    if (x < 3.75f) {
        float t = x * (1.0f / 3.75f);
        t *= t;
        return 1.0f + t * (3.5156229f + t * (3.0899424f + t * (1.2067492f +
                     t * (0.2659732f + t * (0.0360768f + t * 0.0045813f)))));
    } else {
        float t = 3.75f / x;
        float p = 0.39894228f + t * (0.01328592f + t * (0.00225319f +
                  t * (-0.00157565f + t * (0.00916281f + t * (-0.02057706f +
                  t * (0.02635537f + t * (-0.01647633f + t * 0.00392377f)))))));
        return __expf(x) * rsqrtf(x) * p;
    }
}

// ---------------------------------------------------------------------------
__global__ void zero_kernel()
{
    float4* p = reinterpret_cast<float4*>(g_grid);
    const int n = GRID_F2 / 2;
    for (int i = blockIdx.x * blockDim.x + threadIdx.x; i < n;
         i += gridDim.x * blockDim.x)
        p[i] = make_float4(0.f, 0.f, 0.f, 0.f);
}

// ---------------------------------------------------------------------------
__global__ __launch_bounds__(256)
void scatter_kernel(const float* __restrict__ yr, const float* __restrict__ yi,
                    const float* __restrict__ uv, const float* __restrict__ wts)
{
    int m = blockIdx.x * blockDim.x + threadIdx.x;
    if (m >= MPTS) return;

    const float2 c2 = reinterpret_cast<const float2*>(uv)[m];
    const float wt = wts[m];
    const float inv_i0b = 1.0f / bessel_i0(BETA_F);

    int ixv[JW], iyv[JW];
    float wx[JW], wy[JW];

    {
        float k  = c2.x / (2.0f * PI_F) * (float)KGRID;
        float km = floorf(k - 3.0f);
        #pragma unroll
        for (int j = 0; j < JW; j++) {
            float pt = km + (float)(j + 1);
            float d  = k - pt;
            float arg = fmaxf(1.0f - d * d * (1.0f / 9.0f), 0.0f);
            wx[j] = bessel_i0(BETA_F * sqrtf(arg)) * inv_i0b;
            ixv[j] = ((int)pt + KGRID) & (KGRID - 1);
        }
    }
    {
        float k  = c2.y / (2.0f * PI_F) * (float)KGRID;
        float km = floorf(k - 3.0f);
        #pragma unroll
        for (int j = 0; j < JW; j++) {
            float pt = km + (float)(j + 1);
            float d  = k - pt;
            float arg = fmaxf(1.0f - d * d * (1.0f / 9.0f), 0.0f);
            wy[j] = bessel_i0(BETA_F * sqrtf(arg)) * inv_i0b;
            iyv[j] = ((int)pt + KGRID) & (KGRID - 1);
        }
    }

    float yrw[BATCH], yiw[BATCH];
    #pragma unroll
    for (int b = 0; b < BATCH; b++) {
        yrw[b] = yr[b * MPTS + m] * wt;
        yiw[b] = yi[b * MPTS + m] * wt;
    }

    #pragma unroll
    for (int a = 0; a < JW; a++) {
        const int rowbase = ixv[a] * KGRID;
        const float wxa = wx[a];
        #pragma unroll
        for (int c = 0; c < JW; c++) {
            const float w2 = wxa * wy[c];
            float* fp = reinterpret_cast<float*>(&g_grid[(rowbase + iyv[c]) * BATCH]);
            #pragma unroll
            for (int b = 0; b < BATCH; b += 2) {
                asm volatile(
                    "red.global.add.v4.f32 [%0], {%1, %2, %3, %4};"
                    :: "l"(fp + 2 * b),
                       "f"(w2 * yrw[b]),     "f"(w2 * yiw[b]),
                       "f"(w2 * yrw[b + 1]), "f"(w2 * yiw[b + 1])
                    : "memory");
            }
        }
    }
}

// ---------------------------------------------------------------------------
// Register FFT-32 machinery (inverse transform, e^{+i} kernel)
// Tables in __constant__ so they're visible in device code; all indices are
// compile-time constants after full unrolling, so they fold to immediates.
// ---------------------------------------------------------------------------
__device__ __constant__ float W32C[16] = {
    1.0f, 0.98078528f, 0.92387953f, 0.83146961f,
    0.70710678f, 0.55557023f, 0.38268343f, 0.19509032f,
    0.0f, -0.19509032f, -0.38268343f, -0.55557023f,
    -0.70710678f, -0.83146961f, -0.92387953f, -0.98078528f };
__device__ __constant__ float W32S[16] = {
    0.0f, 0.19509032f, 0.38268343f, 0.55557023f,
    0.70710678f, 0.83146961f, 0.92387953f, 0.98078528f,
    1.0f, 0.98078528f, 0.92387953f, 0.83146961f,
    0.70710678f, 0.55557023f, 0.38268343f, 0.19509032f };
__device__ __constant__ int REV5[32] = {
    0,16,8,24,4,20,12,28,2,18,10,26,6,22,14,30,
    1,17,9,25,5,21,13,29,3,19,11,27,7,23,15,31 };

__device__ __forceinline__ float2 cmul(float2 a, float2 b)
{
    return make_float2(a.x * b.x - a.y * b.y, a.x * b.y + a.y * b.x);
}

// DIF radix-2, natural input, bit-reversed output (X[k] at v[rev5(k)]).
__device__ __forceinline__ void fft32_dif(float2 v[32])
{
    #pragma unroll
    for (int s = 0; s < 5; s++) {
        const int m  = 32 >> s;
        const int hm = m >> 1;
        #pragma unroll
        for (int blk = 0; blk < 32; blk += m) {
            #pragma unroll
            for (int j = 0; j < hm; j++) {
                float2 a = v[blk + j];
                float2 b = v[blk + j + hm];
                v[blk + j] = make_float2(a.x + b.x, a.y + b.y);
                float2 d = make_float2(a.x - b.x, a.y - b.y);
                if (j == 0) {
                    v[blk + j + hm] = d;
                } else {
                    const float wc = W32C[j << s];
                    const float ws = W32S[j << s];
                    v[blk + j + hm] = make_float2(d.x * wc - d.y * ws,
                                                  d.x * ws + d.y * wc);
                }
            }
        }
    }
}

// swizzled smem index for logical element n (within one FFT row)
__device__ __forceinline__ int swz(int n)
{
    int a = n >> 5, b = n & 31;
    return (a << 5) | (b ^ a);
}

// Full 1024-pt inverse FFT over the 8 rows held in smem (data, pitch PITCH).
// 256 threads = 8 rows x 32. Caller synced before entry; synced on exit.
__device__ __forceinline__ void fft8x1024_regs(float2* data, int tid)
{
    const int c = tid >> 5;
    const int l = tid & 31;          // n2 for step A, k1' for step B
    float2* row = data + c * PITCH;
    float2 v[32];

    // ---- step A: FFT32 over n1 (stride 32), twiddle, write B[k1, n2] ----
    #pragma unroll
    for (int n1 = 0; n1 < 32; n1++)
        v[n1] = row[(n1 << 5) | (l ^ n1)];
    fft32_dif(v);

    float sw_, cw_;
    __sincosf((float)l * (2.0f * PI_F / 1024.0f), &sw_, &cw_);
    float2 w1 = make_float2(cw_, sw_);
    float2 w2 = cmul(w1, w1);
    float2 w4 = cmul(w2, w2);
    float2 r0 = make_float2(1.0f, 0.0f);
    float2 r1 = w1, r2 = w2, r3 = cmul(w2, w1);
    #pragma unroll
    for (int k1 = 0; k1 < 32; k1 += 4) {
        row[((k1 + 0) << 5) | (l ^ (k1 + 0))] = cmul(v[REV5[k1 + 0]], r0);
        row[((k1 + 1) << 5) | (l ^ (k1 + 1))] = cmul(v[REV5[k1 + 1]], r1);
        row[((k1 + 2) << 5) | (l ^ (k1 + 2))] = cmul(v[REV5[k1 + 2]], r2);
        row[((k1 + 3) << 5) | (l ^ (k1 + 3))] = cmul(v[REV5[k1 + 3]], r3);
        r0 = cmul(r0, w4); r1 = cmul(r1, w4);
        r2 = cmul(r2, w4); r3 = cmul(r3, w4);
    }
    __syncthreads();

    // ---- step B: FFT32 over n2 (unit stride), write X[k1' + 32*k2] ----
    #pragma unroll
    for (int n2 = 0; n2 < 32; n2++)
        v[n2] = row[(l << 5) | (n2 ^ l)];
    __syncthreads();                 // all reads done before cross-row writes
    fft32_dif(v);
    #pragma unroll
    for (int p = 0; p < 32; p++) {
        const int k2 = REV5[p];
        row[(k2 << 5) | (l ^ k2)] = v[p];   // X[k] at swz(k), k = l + 32*k2
    }
    __syncthreads();
}

// ---------------------------------------------------------------------------
// FFT along kx. Block = one iy (8 batches). Pruned output rows.
// ---------------------------------------------------------------------------
__global__ __launch_bounds__(256)
void fft_x_kernel()
{
    extern __shared__ float2 data[];          // 8 * PITCH float2
    const int tid = threadIdx.x;
    const int iy  = blockIdx.x;

    for (int t = tid; t < 8 * KGRID; t += 256) {
        int ix = t >> 3;
        int c  = t & 7;                        // batch
        data[c * PITCH + swz(ix)] = g_grid[ix * (KGRID * BATCH) + iy * BATCH + c];
    }
    __syncthreads();

    fft8x1024_regs(data, tid);

    for (int t = tid; t < 8 * 512; t += 256) {
        int xl = t >> 3;
        int c  = t & 7;
        int xg = (xl < 256) ? xl : xl + 512;   // rows kept after shift+crop
        g_grid[xg * (KGRID * BATCH) + iy * BATCH + c] = data[c * PITCH + swz(xg)];
    }
}

// ---------------------------------------------------------------------------
__device__ __forceinline__ float inv_apod(int i)
{
    float xv = ((float)i - 256.0f) * (1.0f / 1024.0f);
    float pj = PI_F * 6.0f * xv;
    float tv = BETA_F * BETA_F - pj * pj;
    float st = sqrtf(fabsf(tv));
    float num = (tv > 0.0f) ? sinhf(st) : sinf(st);
    return fmaxf(st, 1e-6f) / num;
}

// FFT along ky for one surviving x row (8 batches) + fused epilogue.
__global__ __launch_bounds__(256)
void fft_y_kernel(float* __restrict__ out)
{
    extern __shared__ float2 data[];          // 8 * PITCH float2
    const int tid = threadIdx.x;
    const int x_img = blockIdx.x;
    const int x_src = (x_img + 768) & (KGRID - 1);
    const float2* grow = &g_grid[x_src * (KGRID * BATCH)];

    for (int t = tid; t < 8 * KGRID; t += 256) {
        int iy = t >> 3;
        int c  = t & 7;                        // batch
        data[c * PITCH + swz(iy)] = grow[t];
    }
    __syncthreads();

    fft8x1024_regs(data, tid);

    const float iax = inv_apod(x_img);
    for (int t = tid; t < 8 * NIMG; t += 256) {
        int b  = t >> 9;
        int yi = t & 511;
        int ys = (yi + 768) & (KGRID - 1);
        float v = data[b * PITCH + swz(ys)].x;
        out[b * (NIMG * NIMG) + x_img * NIMG + yi] = v * iax * inv_apod(yi);
    }
}

// ---------------------------------------------------------------------------
extern "C" void kernel_launch(void* const* d_in, const int* in_sizes, int n_in,
                              void* d_out, int out_size)
{
    const float* yr  = (const float*)d_in[0];
    const float* yi  = (const float*)d_in[1];
    const float* uv  = (const float*)d_in[2];
    const float* wts = (const float*)d_in[3];
    float* out = (float*)d_out;

    const int smem_fft = 8 * PITCH * (int)sizeof(float2);   // 65.6 KB
    cudaFuncSetAttribute(fft_x_kernel,
                         cudaFuncAttributeMaxDynamicSharedMemorySize, smem_fft);
    cudaFuncSetAttribute(fft_y_kernel,
                         cudaFuncAttributeMaxDynamicSharedMemorySize, smem_fft);

    zero_kernel<<<4096, 256>>>();
    scatter_kernel<<<(MPTS + 255) / 256, 256>>>(yr, yi, uv, wts);
    fft_x_kernel<<<KGRID, 256, smem_fft>>>();
    fft_y_kernel<<<NIMG, 256, smem_fft>>>(out);
}

// round 5
// speedup vs baseline: 1.5315x; 1.5315x over previous
#include <cuda_runtime.h>
#include <math.h>

// ---------------------------------------------------------------------------
// NUFFT adjoint (Kaiser-Bessel gridding) for GB300 — round 5
// R2 radix-4 smem FFT, upgraded: 512-thread blocks (8 FFTs, 3 blocks/SM),
// PITCH=1026 + float4 stage-0 (all data accesses conflict-free),
// per-stage packed twiddle triplets (conflict-free twiddle reads).
// ---------------------------------------------------------------------------

#define KGRID   1024
#define NIMG    512
#define MPTS    200000
#define BATCH   8
#define JW      6
#define BETA_F  14.04f
#define PI_F    3.14159265358979f

#define GRID_F2 (KGRID * KGRID * BATCH)   // 64 MB
#define PITCH   1026                      // smem row pitch (float2), even

// packed twiddle table: per stage s=1..4, entries [off + 3*j + k], k=0..2
// holding W^em, W^2em, W^3em with em = j << (8 - 2s), W = e^{+2 pi i/1024}
#define TW_OFF1 0
#define TW_OFF2 12
#define TW_OFF3 60
#define TW_OFF4 252
#define TW_TOT  1020

__device__ float2 g_grid[GRID_F2];

// ---------------------------------------------------------------------------
__device__ __forceinline__ float bessel_i0(float x)
{
    if (x < 3.75f) {
        float t = x * (1.0f / 3.75f);
        t *= t;
        return 1.0f + t * (3.5156229f + t * (3.0899424f + t * (1.2067492f +
                     t * (0.2659732f + t * (0.0360768f + t * 0.0045813f)))));
    } else {
        float t = 3.75f / x;
        float p = 0.39894228f + t * (0.01328592f + t * (0.00225319f +
                  t * (-0.00157565f + t * (0.00916281f + t * (-0.02057706f +
                  t * (0.02635537f + t * (-0.01647633f + t * 0.00392377f)))))));
        return __expf(x) * rsqrtf(x) * p;
    }
}

// ---------------------------------------------------------------------------
__global__ void zero_kernel()
{
    float4* p = reinterpret_cast<float4*>(g_grid);
    const int n = GRID_F2 / 2;
    for (int i = blockIdx.x * blockDim.x + threadIdx.x; i < n;
         i += gridDim.x * blockDim.x)
        p[i] = make_float4(0.f, 0.f, 0.f, 0.f);
}

// ---------------------------------------------------------------------------
__global__ __launch_bounds__(256)
void scatter_kernel(const float* __restrict__ yr, const float* __restrict__ yi,
                    const float* __restrict__ uv, const float* __restrict__ wts)
{
    int m = blockIdx.x * blockDim.x + threadIdx.x;
    if (m >= MPTS) return;

    const float2 c2 = reinterpret_cast<const float2*>(uv)[m];
    const float wt = wts[m];
    const float inv_i0b = 1.0f / bessel_i0(BETA_F);

    int ixv[JW], iyv[JW];
    float wx[JW], wy[JW];

    {
        float k  = c2.x / (2.0f * PI_F) * (float)KGRID;
        float km = floorf(k - 3.0f);
        #pragma unroll
        for (int j = 0; j < JW; j++) {
            float pt = km + (float)(j + 1);
            float d  = k - pt;
            float arg = fmaxf(1.0f - d * d * (1.0f / 9.0f), 0.0f);
            wx[j] = bessel_i0(BETA_F * sqrtf(arg)) * inv_i0b;
            ixv[j] = ((int)pt + KGRID) & (KGRID - 1);
        }
    }
    {
        float k  = c2.y / (2.0f * PI_F) * (float)KGRID;
        float km = floorf(k - 3.0f);
        #pragma unroll
        for (int j = 0; j < JW; j++) {
            float pt = km + (float)(j + 1);
            float d  = k - pt;
            float arg = fmaxf(1.0f - d * d * (1.0f / 9.0f), 0.0f);
            wy[j] = bessel_i0(BETA_F * sqrtf(arg)) * inv_i0b;
            iyv[j] = ((int)pt + KGRID) & (KGRID - 1);
        }
    }

    float yrw[BATCH], yiw[BATCH];
    #pragma unroll
    for (int b = 0; b < BATCH; b++) {
        yrw[b] = yr[b * MPTS + m] * wt;
        yiw[b] = yi[b * MPTS + m] * wt;
    }

    #pragma unroll
    for (int a = 0; a < JW; a++) {
        const int rowbase = ixv[a] * KGRID;
        const float wxa = wx[a];
        #pragma unroll
        for (int c = 0; c < JW; c++) {
            const float w2 = wxa * wy[c];
            float* fp = reinterpret_cast<float*>(&g_grid[(rowbase + iyv[c]) * BATCH]);
            #pragma unroll
            for (int b = 0; b < BATCH; b += 2) {
                asm volatile(
                    "red.global.add.v4.f32 [%0], {%1, %2, %3, %4};"
                    :: "l"(fp + 2 * b),
                       "f"(w2 * yrw[b]),     "f"(w2 * yiw[b]),
                       "f"(w2 * yrw[b + 1]), "f"(w2 * yiw[b + 1])
                    : "memory");
            }
        }
    }
}

// ---------------------------------------------------------------------------
// Radix-4 FFT machinery (inverse, e^{+i})
// ---------------------------------------------------------------------------
__device__ __forceinline__ int digit_rev10(int i)
{
    int r = (int)(__brev((unsigned)i) >> 22);               // bit-reverse 10b
    return ((r & 0x155) << 1) | ((r & 0x2AA) >> 1);         // swap bit pairs
}

__device__ __forceinline__ float2 cmul(float2 a, float2 b)
{
    return make_float2(a.x * b.x - a.y * b.y, a.x * b.y + a.y * b.x);
}

// build packed per-stage twiddle triplets
__device__ __forceinline__ void init_tw(float2* tw, int tid, int nthr)
{
    for (int t = tid; t < 340; t += nthr) {
        int s, j, off;
        if      (t < 4)  { s = 1; j = t;      off = TW_OFF1; }
        else if (t < 20) { s = 2; j = t - 4;  off = TW_OFF2; }
        else if (t < 84) { s = 3; j = t - 20; off = TW_OFF3; }
        else             { s = 4; j = t - 84; off = TW_OFF4; }
        int em = j << (8 - 2 * s);
        float a = (float)em * (2.0f * PI_F / 1024.0f);
        float s1, c1, s2, c2, s3, c3;
        __sincosf(a, &s1, &c1);
        __sincosf(2.0f * a, &s2, &c2);
        __sincosf(3.0f * a, &s3, &c3);
        tw[off + 3 * j + 0] = make_float2(c1, s1);
        tw[off + 3 * j + 1] = make_float2(c2, s2);
        tw[off + 3 * j + 2] = make_float2(c3, s3);
    }
}

// radix-4 inverse combine
__device__ __forceinline__ void rad4(float2 b0, float2 b1, float2 b2, float2 b3,
                                     float2& y0, float2& y1, float2& y2, float2& y3)
{
    float2 t0 = make_float2(b0.x + b2.x, b0.y + b2.y);
    float2 t1 = make_float2(b0.x - b2.x, b0.y - b2.y);
    float2 t2 = make_float2(b1.x + b3.x, b1.y + b3.y);
    float2 t3 = make_float2(-(b1.y - b3.y), b1.x - b3.x);   // +i*(b1-b3)
    y0 = make_float2(t0.x + t2.x, t0.y + t2.y);
    y1 = make_float2(t1.x + t3.x, t1.y + t3.y);
    y2 = make_float2(t0.x - t2.x, t0.y - t2.y);
    y3 = make_float2(t1.x - t3.x, t1.y - t3.y);
}

template<int S, int OFF>
__device__ __forceinline__ void stage4(float2* x, const float2* tw, int bi0)
{
    const int sh = 2 * S;
    const int quarter = 1 << sh;
    #pragma unroll
    for (int u = 0; u < 4; u++) {
        const int bi = bi0 + (u << 6);
        const int j  = bi & (quarter - 1);
        const int base = ((bi >> sh) << (sh + 2)) | j;
        float2 b0 = x[base];
        float2 b1 = x[base + quarter];
        float2 b2 = x[base + 2 * quarter];
        float2 b3 = x[base + 3 * quarter];
        float2 w1 = tw[OFF + 3 * j + 0];
        float2 w2 = tw[OFF + 3 * j + 1];
        float2 w3 = tw[OFF + 3 * j + 2];
        b1 = cmul(b1, w1);
        b2 = cmul(b2, w2);
        b3 = cmul(b3, w3);
        float2 y0, y1, y2, y3;
        rad4(b0, b1, b2, b3, y0, y1, y2, y3);
        x[base]               = y0;
        x[base + quarter]     = y1;
        x[base + 2 * quarter] = y2;
        x[base + 3 * quarter] = y3;
    }
}

// 8 independent 1024-pt inverse FFTs; 512 threads; data rows pitch PITCH.
// Stage 0: float4-vectorized, twiddle-free, fft-major (conflict-free).
// Stage 1: fft-major; stages 2-4: element-major (all conflict-free).
__device__ __forceinline__ void fft8x1024(float2* data, const float2* tw, int tid)
{
    {   // stage 0
        float4* xv = reinterpret_cast<float4*>(data + (tid & 7) * PITCH);
        const int bi0 = tid >> 3;
        #pragma unroll
        for (int u = 0; u < 4; u++) {
            const int bi = bi0 + (u << 6);
            float4 f01 = xv[2 * bi];
            float4 f23 = xv[2 * bi + 1];
            float2 y0, y1, y2, y3;
            rad4(make_float2(f01.x, f01.y), make_float2(f01.z, f01.w),
                 make_float2(f23.x, f23.y), make_float2(f23.z, f23.w),
                 y0, y1, y2, y3);
            xv[2 * bi]     = make_float4(y0.x, y0.y, y1.x, y1.y);
            xv[2 * bi + 1] = make_float4(y2.x, y2.y, y3.x, y3.y);
        }
        __syncthreads();
    }
    stage4<1, TW_OFF1>(data + (tid & 7) * PITCH, tw, tid >> 3);
    __syncthreads();
    stage4<2, TW_OFF2>(data + (tid >> 6) * PITCH, tw, tid & 63);
    __syncthreads();
    stage4<3, TW_OFF3>(data + (tid >> 6) * PITCH, tw, tid & 63);
    __syncthreads();
    stage4<4, TW_OFF4>(data + (tid >> 6) * PITCH, tw, tid & 63);
    __syncthreads();
}

// ---------------------------------------------------------------------------
// FFT along kx. Block = one iy (8 batch FFTs). Pruned output rows.
// ---------------------------------------------------------------------------
__global__ __launch_bounds__(512, 3)
void fft_x_kernel()
{
    extern __shared__ float2 sm[];
    float2* tw   = sm;                        // TW_TOT
    float2* data = sm + TW_TOT;               // 8 * PITCH
    const int tid = threadIdx.x;
    init_tw(tw, tid, 512);

    const int iy = blockIdx.x;

    for (int t = tid; t < 8 * KGRID; t += 512) {
        int ix = t >> 3;
        int c  = t & 7;                        // batch
        data[c * PITCH + digit_rev10(ix)] =
            g_grid[ix * (KGRID * BATCH) + iy * BATCH + c];
    }
    __syncthreads();

    fft8x1024(data, tw, tid);

    for (int t = tid; t < 8 * 512; t += 512) {
        int xl = t >> 3;
        int c  = t & 7;
        int xg = (xl < 256) ? xl : xl + 512;   // rows kept after shift+crop
        g_grid[xg * (KGRID * BATCH) + iy * BATCH + c] = data[c * PITCH + xg];
    }
}

// ---------------------------------------------------------------------------
__device__ __forceinline__ float inv_apod(int i)
{
    float xv = ((float)i - 256.0f) * (1.0f / 1024.0f);
    float pj = PI_F * 6.0f * xv;
    float tv = BETA_F * BETA_F - pj * pj;
    float st = sqrtf(fabsf(tv));
    float num = (tv > 0.0f) ? sinhf(st) : sinf(st);
    return fmaxf(st, 1e-6f) / num;
}

// FFT along ky for one surviving x row (8 batches) + fused epilogue.
__global__ __launch_bounds__(512, 3)
void fft_y_kernel(float* __restrict__ out)
{
    extern __shared__ float2 sm[];
    float2* tw   = sm;
    float2* data = sm + TW_TOT;
    const int tid = threadIdx.x;
    init_tw(tw, tid, 512);

    const int x_img = blockIdx.x;
    const int x_src = (x_img + 768) & (KGRID - 1);
    const float2* grow = &g_grid[x_src * (KGRID * BATCH)];

    for (int t = tid; t < 8 * KGRID; t += 512) {
        int iy = t >> 3;
        int c  = t & 7;                        // batch
        data[c * PITCH + digit_rev10(iy)] = grow[t];
    }
    __syncthreads();

    fft8x1024(data, tw, tid);

    const float iax = inv_apod(x_img);
    for (int t = tid; t < 8 * NIMG; t += 512) {
        int b  = t >> 9;
        int yi = t & 511;
        int ys = (yi + 768) & (KGRID - 1);
        float v = data[b * PITCH + ys].x;
        out[b * (NIMG * NIMG) + x_img * NIMG + yi] = v * iax * inv_apod(yi);
    }
}

// ---------------------------------------------------------------------------
extern "C" void kernel_launch(void* const* d_in, const int* in_sizes, int n_in,
                              void* d_out, int out_size)
{
    const float* yr  = (const float*)d_in[0];
    const float* yi  = (const float*)d_in[1];
    const float* uv  = (const float*)d_in[2];
    const float* wts = (const float*)d_in[3];
    float* out = (float*)d_out;

    const int smem_fft = (TW_TOT + 8 * PITCH) * (int)sizeof(float2); // ~73.8 KB
    cudaFuncSetAttribute(fft_x_kernel,
                         cudaFuncAttributeMaxDynamicSharedMemorySize, smem_fft);
    cudaFuncSetAttribute(fft_y_kernel,
                         cudaFuncAttributeMaxDynamicSharedMemorySize, smem_fft);

    zero_kernel<<<4096, 256>>>();
    scatter_kernel<<<(MPTS + 255) / 256, 256>>>(yr, yi, uv, wts);
    fft_x_kernel<<<KGRID, 512, smem_fft>>>();
    fft_y_kernel<<<NIMG, 512, smem_fft>>>(out);
}